// round 8
// baseline (speedup 1.0000x reference)
#include <cuda_runtime.h>
#include <math.h>

#define Hdim 512
#define G4   2048
#define NB   256      // B*U lstm lanes
#define LT   64       // timesteps
#define BB   8
#define UU   32
#define SS   2048
#define EE   128
#define NNODE 33      // U+1
#define LSTM_GRID 128

typedef unsigned long long u64;

__device__ __forceinline__ u64 pk2(float lo, float hi){
  u64 r; asm("mov.b64 %0, {%1,%2};" : "=l"(r) : "r"(__float_as_uint(lo)), "r"(__float_as_uint(hi))); return r;
}
__device__ __forceinline__ u64 fma2(u64 a, u64 b, u64 c){
  u64 d; asm("fma.rn.f32x2 %0, %1, %2, %3;" : "=l"(d) : "l"(a), "l"(b), "l"(c)); return d;
}
__device__ __forceinline__ u64 add2(u64 a, u64 b){
  u64 d; asm("add.rn.f32x2 %0, %1, %2;" : "=l"(d) : "l"(a), "l"(b)); return d;
}
__device__ __forceinline__ void upk2(u64 v, float& lo, float& hi){
  unsigned l_, h_; asm("mov.b64 {%0,%1}, %2;" : "=r"(l_), "=r"(h_) : "l"(v));
  lo = __uint_as_float(l_); hi = __uint_as_float(h_);
}

// ---------------- scratch (device globals; no allocations allowed) ----------
__device__ float g_x  [(size_t)LT*NB*Hdim];
__device__ float g_gx [(size_t)LT*NB*G4];
__device__ float g_ys [(size_t)LT*NB*Hdim];
__device__ float g_h  [2][NB*Hdim];
__device__ float g_nodes[BB*NNODE*Hdim];
__device__ float g_msg  [(size_t)BB*EE*Hdim];
__device__ float g_agg  [BB*NNODE*Hdim];
__device__ float g_new  [BB*NNODE*Hdim];
__device__ unsigned g_bar4[4];

// ---------------- output offsets (pytree flatten order) ---------------------
#define OFF_ENCH 0
#define OFF_ENCC 4096
#define OFF_MB   8192
#define OFF_LEN1 (8192 + 8388608)
#define OFF_MBU  (OFF_LEN1 + 8)
#define OFF_LEN2 (OFF_MBU + 8388608)
#define OFF_HIER (OFF_LEN2 + 8)

__device__ __forceinline__ float sigmf(float x){ return 1.0f/(1.0f+expf(-x)); }

// ---------------- init: zero h0, barriers ------------------------------------
__global__ void k_zero(){
  int i = blockIdx.x*blockDim.x + threadIdx.x;
  if (i < NB*Hdim){ g_h[0][i] = 0.0f; }
  if (i < 4) g_bar4[i] = 0u;
}

// ---------------- embedding gather -----------------------------------------
__global__ void k_embed(const int* __restrict__ src, const int* __restrict__ speaker,
                        const float* __restrict__ emb, const float* __restrict__ spkt){
  int row = blockIdx.x;            // t*256 + n
  int t = row >> 8, n = row & 255;
  int b = n >> 5, u = n & 31;
  int s = u*LT + t;
  int w  = src[s*BB + b];
  int sp = speaker[b*SS + s];
  const float* er = emb  + (size_t)w  * Hdim;
  const float* sr = spkt + (size_t)sp * Hdim;
  float* xr = g_x + (size_t)row * Hdim;
  for (int h = threadIdx.x; h < Hdim; h += blockDim.x)
    xr[h] = er[h] + sr[h];
}

// ---------------- Gx = x @ W_ih + b ; M=16384 N=2048 K=512 ------------------
// 128x64 tile, 256 threads, 8 rows x 4 cols per thread via f32x2.
#define GX_PAD 130
__global__ void __launch_bounds__(256) k_gx_gemm(const float* __restrict__ Wih,
                                                 const float* __restrict__ bias){
  __shared__ float As[2][16][GX_PAD];
  __shared__ float Bs[2][16][64];
  int tid = threadIdx.x;
  int m0 = blockIdx.y*128, n0 = blockIdx.x*64;
  int tr = tid>>4, tc = tid&15;
  int s_arow = tid>>2, s_ak = (tid&3)<<2;
  int s_bk = tid>>4, s_bn = (tid&15)<<2;

  const float* Ap = g_x + (size_t)(m0 + s_arow)*Hdim + s_ak;
  const float* Bp = Wih + (size_t)s_bk*G4 + n0 + s_bn;

  float4 ra0 = *(const float4*)Ap;
  float4 ra1 = *(const float4*)(Ap + (size_t)64*Hdim);
  float4 rb  = *(const float4*)Bp;

  u64 acc[4][4];
  #pragma unroll
  for (int r=0;r<4;r++){ acc[r][0]=0; acc[r][1]=0; acc[r][2]=0; acc[r][3]=0; }

  int buf = 0;
  for (int k0 = 0; k0 < Hdim; k0 += 16){
    As[buf][s_ak+0][s_arow]    = ra0.x; As[buf][s_ak+1][s_arow]    = ra0.y;
    As[buf][s_ak+2][s_arow]    = ra0.z; As[buf][s_ak+3][s_arow]    = ra0.w;
    As[buf][s_ak+0][s_arow+64] = ra1.x; As[buf][s_ak+1][s_arow+64] = ra1.y;
    As[buf][s_ak+2][s_arow+64] = ra1.z; As[buf][s_ak+3][s_arow+64] = ra1.w;
    *(float4*)&Bs[buf][s_bk][s_bn] = rb;
    __syncthreads();
    if (k0 + 16 < Hdim){
      Ap += 16; Bp += (size_t)16*G4;
      ra0 = *(const float4*)Ap;
      ra1 = *(const float4*)(Ap + (size_t)64*Hdim);
      rb  = *(const float4*)Bp;
    }
    #pragma unroll
    for (int kk = 0; kk < 16; kk++){
      const float* Ak = &As[buf][kk][tr<<3];
      u64 a0 = *(const u64*)(Ak);
      u64 a1 = *(const u64*)(Ak+2);
      u64 a2 = *(const u64*)(Ak+4);
      u64 a3 = *(const u64*)(Ak+6);
      float4 b = *(const float4*)&Bs[buf][kk][tc<<2];
      u64 b0 = pk2(b.x,b.x), b1 = pk2(b.y,b.y), b2 = pk2(b.z,b.z), b3 = pk2(b.w,b.w);
      acc[0][0]=fma2(a0,b0,acc[0][0]); acc[0][1]=fma2(a0,b1,acc[0][1]);
      acc[0][2]=fma2(a0,b2,acc[0][2]); acc[0][3]=fma2(a0,b3,acc[0][3]);
      acc[1][0]=fma2(a1,b0,acc[1][0]); acc[1][1]=fma2(a1,b1,acc[1][1]);
      acc[1][2]=fma2(a1,b2,acc[1][2]); acc[1][3]=fma2(a1,b3,acc[1][3]);
      acc[2][0]=fma2(a2,b0,acc[2][0]); acc[2][1]=fma2(a2,b1,acc[2][1]);
      acc[2][2]=fma2(a2,b2,acc[2][2]); acc[2][3]=fma2(a2,b3,acc[2][3]);
      acc[3][0]=fma2(a3,b0,acc[3][0]); acc[3][1]=fma2(a3,b1,acc[3][1]);
      acc[3][2]=fma2(a3,b2,acc[3][2]); acc[3][3]=fma2(a3,b3,acc[3][3]);
    }
    buf ^= 1;
  }
  int mrow = m0 + (tr<<3);
  int ncol = n0 + (tc<<2);
  float b0 = bias[ncol], b1 = bias[ncol+1], b2 = bias[ncol+2], b3 = bias[ncol+3];
  #pragma unroll
  for (int rp = 0; rp < 4; rp++){
    float r0c0,r1c0,r0c1,r1c1,r0c2,r1c2,r0c3,r1c3;
    upk2(acc[rp][0], r0c0, r1c0);
    upk2(acc[rp][1], r0c1, r1c1);
    upk2(acc[rp][2], r0c2, r1c2);
    upk2(acc[rp][3], r0c3, r1c3);
    *(float4*)&g_gx[(size_t)(mrow + rp*2    )*G4 + ncol] = make_float4(r0c0+b0, r0c1+b1, r0c2+b2, r0c3+b3);
    *(float4*)&g_gx[(size_t)(mrow + rp*2 + 1)*G4 + ncol] = make_float4(r1c0+b0, r1c1+b1, r1c2+b2, r1c3+b3);
  }
}

// ---------------- persistent LSTM: all 64 steps, split-K, 512 threads -------
// grid = 128 CTAs = 4 row-tiles(64 rows) x 32 hidden-slices(16 units).
// threads: kh = tid>>8 (k-half), th = tid&255 : rg (16 x 4rows) x jh (16 units)
#define AS_PAD 66
#define WS_FLOATS (512*64)
#define SMEM_LSTM ((WS_FLOATS + 2*2*32*AS_PAD) * 4)

extern __shared__ float smem_dyn[];

__global__ void __launch_bounds__(512) k_lstm_persist(const float* __restrict__ Whh){
  float* Ws = smem_dyn;                 // [k][jh*4+g]
  float* As = smem_dyn + WS_FLOATS;     // [buf2][kh2][32][AS_PAD]
  int tid = threadIdx.x;
  int hs = blockIdx.x & 31;
  int mt = blockIdx.x >> 5;
  int m0 = mt << 6;

  // load Whh slice into SMEM once
  {
    int jh = tid & 15, g = (tid>>4)&3, kq = tid>>6;   // kq 0..7
    for (int k = kq; k < 512; k += 8)
      Ws[k*64 + jh*4 + g] = Whh[(size_t)k*G4 + g*512 + hs*16 + jh];
  }
  __syncthreads();

  int kh = tid >> 8;            // k-half 0/1
  int th = tid & 255;
  int rg = th >> 4;             // 0..15 rowgroups of 4
  int jh = th & 15;
  int jglob = hs*16 + jh;
  int r0 = m0 + (rg<<2);
  int khbase = kh << 8;         // 0 / 256

  // A staging map (per half: 256 threads stage 64 rows x 32 k)
  int srow  = th >> 2;          // 0..63
  int skoff = (th & 3) << 3;    // 0,8,16,24

  float cc[4] = {0.f,0.f,0.f,0.f};

  for (int t = 0; t < LT; t++){
    const float* hprev = g_h[t & 1];
    float*       hnext = g_h[(t+1) & 1];

    // epilogue gx prefetch (half-0 only; hides under k-loop)
    float pi[4], pf[4], pg[4], po[4];
    if (kh == 0){
      const float* gx = g_gx + (size_t)t*NB*G4;
      #pragma unroll
      for (int rr = 0; rr < 4; rr++){
        const float* gb = gx + (size_t)(r0+rr)*G4 + jglob;
        pi[rr] = __ldcg(gb);
        pf[rr] = __ldcg(gb + 512);
        pg[rr] = __ldcg(gb + 1024);
        po[rr] = __ldcg(gb + 1536);
      }
    }

    u64 acc[8];
    #pragma unroll
    for (int i=0;i<8;i++) acc[i] = 0ull;

    const float* hrow = hprev + (size_t)(m0+srow)*Hdim + khbase + skoff;
    float4 p0 = __ldcg((const float4*)hrow);
    float4 p1 = __ldcg((const float4*)(hrow + 4));
    int buf = 0;
    for (int c = 0; c < 8; c++){
      float* A = As + (size_t)((buf<<1) + kh)*32*AS_PAD;
      A[(skoff+0)*AS_PAD + srow] = p0.x;
      A[(skoff+1)*AS_PAD + srow] = p0.y;
      A[(skoff+2)*AS_PAD + srow] = p0.z;
      A[(skoff+3)*AS_PAD + srow] = p0.w;
      A[(skoff+4)*AS_PAD + srow] = p1.x;
      A[(skoff+5)*AS_PAD + srow] = p1.y;
      A[(skoff+6)*AS_PAD + srow] = p1.z;
      A[(skoff+7)*AS_PAD + srow] = p1.w;
      __syncthreads();
      if (c < 7){
        p0 = __ldcg((const float4*)(hrow + (c+1)*32));
        p1 = __ldcg((const float4*)(hrow + (c+1)*32 + 4));
      }
      const float* Wk = Ws + (size_t)(khbase + c*32)*64 + (jh<<2);
      #pragma unroll
      for (int kk = 0; kk < 32; kk++){
        const float* Ak = A + kk*AS_PAD + (rg<<2);
        u64 a01 = *(const u64*)(Ak);
        u64 a23 = *(const u64*)(Ak + 2);
        float4 b = *(const float4*)(Wk + kk*64);
        u64 b0 = pk2(b.x,b.x), b1 = pk2(b.y,b.y);
        u64 b2 = pk2(b.z,b.z), b3 = pk2(b.w,b.w);
        acc[0] = fma2(a01,b0,acc[0]); acc[1] = fma2(a23,b0,acc[1]);
        acc[2] = fma2(a01,b1,acc[2]); acc[3] = fma2(a23,b1,acc[3]);
        acc[4] = fma2(a01,b2,acc[4]); acc[5] = fma2(a23,b2,acc[5]);
        acc[6] = fma2(a01,b3,acc[6]); acc[7] = fma2(a23,b3,acc[7]);
      }
      buf ^= 1;
    }

    // cross-half reduction through SMEM (exact fp32 adds)
    __syncthreads();
    u64* red = (u64*)As;
    if (kh == 1){
      #pragma unroll
      for (int i=0;i<8;i++) red[th*8 + i] = acc[i];
    }
    __syncthreads();
    if (kh == 0){
      #pragma unroll
      for (int i=0;i<8;i++) acc[i] = add2(acc[i], red[th*8 + i]);

      float iv[4], fv[4], gv[4], ov[4];
      upk2(acc[0], iv[0], iv[1]); upk2(acc[1], iv[2], iv[3]);
      upk2(acc[2], fv[0], fv[1]); upk2(acc[3], fv[2], fv[3]);
      upk2(acc[4], gv[0], gv[1]); upk2(acc[5], gv[2], gv[3]);
      upk2(acc[6], ov[0], ov[1]); upk2(acc[7], ov[2], ov[3]);
      float* ys = g_ys + (size_t)t*NB*Hdim;
      #pragma unroll
      for (int rr = 0; rr < 4; rr++){
        int n = r0 + rr;
        float i_ = iv[rr] + pi[rr];
        float f_ = fv[rr] + pf[rr];
        float g_ = gv[rr] + pg[rr];
        float o_ = ov[rr] + po[rr];
        float c_ = sigmf(f_)*cc[rr] + sigmf(i_)*tanhf(g_);
        float h_ = sigmf(o_)*tanhf(c_);
        cc[rr] = c_;
        hnext[(size_t)n*Hdim + jglob] = h_;
        ys   [(size_t)n*Hdim + jglob] = h_;
      }
    }

    // group barrier over the 32 CTAs sharing this row-tile
    if (t < LT-1){
      __threadfence();
      __syncthreads();
      if (tid == 0){
        atomicAdd(&g_bar4[mt], 1u);
        unsigned target = (unsigned)(t+1) * 32u;
        volatile unsigned* vb = &g_bar4[mt];
        while (*vb < target) { }
      }
      __syncthreads();
    }
  }
}

// ---------------- GNN: build nodes ------------------------------------------
__global__ void k_nodes(){
  int b = blockIdx.x, h = threadIdx.x;
  const float* last = g_ys + (size_t)(LT-1)*NB*Hdim;
  float s = 0.0f;
  for (int u = 0; u < UU; u++){
    float v = last[(size_t)(b*UU + u)*Hdim + h];
    g_nodes[(size_t)(b*NNODE + u)*Hdim + h] = v;
    s += v;
  }
  g_nodes[(size_t)(b*NNODE + UU)*Hdim + h] = s * (1.0f/UU);
}

// ---------------- per-edge message ------------------------------------------
__global__ void __launch_bounds__(256) k_msg(const int* __restrict__ edge_src,
                                             const int* __restrict__ rels,
                                             const float* __restrict__ Wrel){
  int be = blockIdx.x;
  int b = be >> 7;
  int rel = rels[be];
  int es  = edge_src[be];
  __shared__ float xs[Hdim];
  int tid = threadIdx.x;
  xs[tid]     = g_nodes[(size_t)(b*NNODE + es)*Hdim + tid];
  xs[tid+256] = g_nodes[(size_t)(b*NNODE + es)*Hdim + tid + 256];
  __syncthreads();
  const float* W = Wrel + (size_t)rel*Hdim*Hdim;
  float a0 = 0.0f, a1 = 0.0f;
  for (int k = 0; k < Hdim; k++){
    float xv = xs[k];
    a0 += xv * W[(size_t)k*Hdim + tid];
    a1 += xv * W[(size_t)k*Hdim + tid + 256];
  }
  g_msg[(size_t)be*Hdim + tid]       = a0;
  g_msg[(size_t)be*Hdim + tid + 256] = a1;
}

// ---------------- deterministic segment-sum ---------------------------------
__global__ void k_agg(const int* __restrict__ edge_dst){
  int bd = blockIdx.x;
  int b = bd / NNODE, d = bd % NNODE;
  int h = threadIdx.x;
  float a = 0.0f;
  for (int e = 0; e < EE; e++){
    if (edge_dst[b*EE + e] == d)
      a += g_msg[(size_t)(b*EE + e)*Hdim + h];
  }
  g_agg[(size_t)bd*Hdim + h] = a;
}

// ---------------- GNN output/gate fusion ------------------------------------
__global__ void __launch_bounds__(256) k_gnn(const float* __restrict__ Wself,
                                             const float* __restrict__ bg,
                                             const float* __restrict__ Wg1,
                                             const float* __restrict__ Wg2){
  int bd = blockIdx.x;
  __shared__ float nd[Hdim], ag[Hdim];
  int tid = threadIdx.x;
  nd[tid]     = g_nodes[(size_t)bd*Hdim + tid];
  nd[tid+256] = g_nodes[(size_t)bd*Hdim + tid + 256];
  ag[tid]     = g_agg[(size_t)bd*Hdim + tid];
  ag[tid+256] = g_agg[(size_t)bd*Hdim + tid + 256];
  __syncthreads();
  for (int jo = 0; jo < 2; jo++){
    int j = tid + jo*256;
    float s1 = 0.0f, s2 = 0.0f, s3 = 0.0f;
    for (int k = 0; k < Hdim; k++){
      float nv = nd[k], av = ag[k];
      s1 += nv * Wself[(size_t)k*Hdim + j];
      s2 += nv * Wg1  [(size_t)k*Hdim + j];
      s3 += av * Wg2  [(size_t)k*Hdim + j];
    }
    float outv = s1 + ag[j] + bg[j];
    outv = outv > 0.0f ? outv : 0.0f;
    float gate = sigmf(s2 + s3);
    g_new[(size_t)bd*Hdim + j] = gate*outv + (1.0f - gate)*nd[j];
  }
}

// ---------------- output writers --------------------------------------------
__global__ void k_out_small(float* __restrict__ dout, const int* __restrict__ lengths){
  int i = blockIdx.x*blockDim.x + threadIdx.x;
  if (i < 4096){
    int b = i >> 9, h = i & 511;
    float v = g_new[(size_t)(b*NNODE + UU)*Hdim + h];
    dout[OFF_ENCH + i] = v;
    dout[OFF_ENCC + i] = v;
  }
  if (i < 8){
    float lv = (float)lengths[i];
    dout[OFF_LEN1 + i] = lv;
    dout[OFF_LEN2 + i] = lv;
  }
  dout[OFF_HIER + i] = (float)LT;
}

__global__ void k_big_out(float* __restrict__ dout){
  size_t i = (size_t)blockIdx.x*blockDim.x + threadIdx.x;
  if (i >= (size_t)SS*BB*Hdim) return;
  int h = (int)(i & 511);
  int b = (int)((i >> 9) & 7);
  int s = (int)(i >> 12);
  int t = s & 63, u = s >> 6;
  dout[OFF_MB  + i] = g_ys[((size_t)t*NB + b*UU + u)*Hdim + h];
  dout[OFF_MBU + i] = g_new[(size_t)(b*NNODE + u)*Hdim + h];
}

// ---------------- driver -----------------------------------------------------
extern "C" void kernel_launch(void* const* d_in, const int* in_sizes, int n_in,
                              void* d_out, int out_size){
  const int*   src      = (const int*)  d_in[0];
  const int*   speaker  = (const int*)  d_in[2];
  const int*   lengths  = (const int*)  d_in[3];
  const int*   edge_src = (const int*)  d_in[4];
  const int*   edge_dst = (const int*)  d_in[5];
  const int*   rels     = (const int*)  d_in[6];
  const float* emb      = (const float*)d_in[7];
  const float* spkt     = (const float*)d_in[8];
  const float* Wih      = (const float*)d_in[9];
  const float* Whh      = (const float*)d_in[10];
  const float* bl       = (const float*)d_in[11];
  const float* Wrel     = (const float*)d_in[12];
  const float* Wself    = (const float*)d_in[13];
  const float* bg       = (const float*)d_in[14];
  const float* Wg1      = (const float*)d_in[15];
  const float* Wg2      = (const float*)d_in[16];
  float* dout = (float*)d_out;

  cudaFuncSetAttribute(k_lstm_persist, cudaFuncAttributeMaxDynamicSharedMemorySize, SMEM_LSTM);

  k_zero<<<512, 256>>>();
  k_embed<<<LT*NB, 256>>>(src, speaker, emb, spkt);
  k_gx_gemm<<<dim3(G4/64, (LT*NB)/128), 256>>>(Wih, bl);
  k_lstm_persist<<<LSTM_GRID, 512, SMEM_LSTM>>>(Whh);
  k_nodes<<<BB, 512>>>();
  k_msg<<<BB*EE, 256>>>(edge_src, rels, Wrel);
  k_agg<<<BB*NNODE, 512>>>(edge_dst);
  k_gnn<<<BB*NNODE, 256>>>(Wself, bg, Wg1, Wg2);
  k_out_small<<<64, 256>>>(dout, lengths);
  k_big_out<<<32768, 256>>>(dout);
}

// round 10
// speedup vs baseline: 1.0243x; 1.0243x over previous
#include <cuda_runtime.h>
#include <math.h>

#define Hdim 512
#define G4   2048
#define NB   256      // B*U lstm lanes
#define LT   64       // timesteps
#define BB   8
#define UU   32
#define SS   2048
#define EE   128
#define NNODE 33      // U+1
#define LSTM_GRID 128

typedef unsigned long long u64;

__device__ __forceinline__ u64 pk2(float lo, float hi){
  u64 r; asm("mov.b64 %0, {%1,%2};" : "=l"(r) : "r"(__float_as_uint(lo)), "r"(__float_as_uint(hi))); return r;
}
__device__ __forceinline__ u64 fma2(u64 a, u64 b, u64 c){
  u64 d; asm("fma.rn.f32x2 %0, %1, %2, %3;" : "=l"(d) : "l"(a), "l"(b), "l"(c)); return d;
}
__device__ __forceinline__ u64 add2(u64 a, u64 b){
  u64 d; asm("add.rn.f32x2 %0, %1, %2;" : "=l"(d) : "l"(a), "l"(b)); return d;
}
__device__ __forceinline__ void upk2(u64 v, float& lo, float& hi){
  unsigned l_, h_; asm("mov.b64 {%0,%1}, %2;" : "=r"(l_), "=r"(h_) : "l"(v));
  lo = __uint_as_float(l_); hi = __uint_as_float(h_);
}

// ---------------- scratch (device globals; no allocations allowed) ----------
__device__ float g_x  [(size_t)LT*NB*Hdim];
__device__ float g_gx [(size_t)LT*NB*G4];
__device__ float g_ys [(size_t)LT*NB*Hdim];
__device__ float g_h  [2][NB*Hdim];
__device__ float g_nodes[BB*NNODE*Hdim];
__device__ float g_msg  [(size_t)BB*EE*Hdim];
__device__ float g_agg  [BB*NNODE*Hdim];
__device__ float g_new  [BB*NNODE*Hdim];
__device__ unsigned g_bar4[4];

// ---------------- output offsets (pytree flatten order) ---------------------
#define OFF_ENCH 0
#define OFF_ENCC 4096
#define OFF_MB   8192
#define OFF_LEN1 (8192 + 8388608)
#define OFF_MBU  (OFF_LEN1 + 8)
#define OFF_LEN2 (OFF_MBU + 8388608)
#define OFF_HIER (OFF_LEN2 + 8)

__device__ __forceinline__ float sigmf(float x){ return 1.0f/(1.0f+expf(-x)); }
// fast variants for the LSTM hot loop (MUFU.EX2 path, IEEE divide for inf-safety)
__device__ __forceinline__ float sigmf_fast(float x){ return 1.0f/(1.0f+__expf(-x)); }
__device__ __forceinline__ float tanh_fast(float x){ return 2.0f/(1.0f+__expf(-2.0f*x)) - 1.0f; }

// ---------------- init: zero h0, barriers ------------------------------------
__global__ void k_zero(){
  int i = blockIdx.x*blockDim.x + threadIdx.x;
  if (i < NB*Hdim){ g_h[0][i] = 0.0f; }
  if (i < 4) g_bar4[i] = 0u;
}

// ---------------- embedding gather -----------------------------------------
__global__ void k_embed(const int* __restrict__ src, const int* __restrict__ speaker,
                        const float* __restrict__ emb, const float* __restrict__ spkt){
  int row = blockIdx.x;            // t*256 + n
  int t = row >> 8, n = row & 255;
  int b = n >> 5, u = n & 31;
  int s = u*LT + t;
  int w  = src[s*BB + b];
  int sp = speaker[b*SS + s];
  const float* er = emb  + (size_t)w  * Hdim;
  const float* sr = spkt + (size_t)sp * Hdim;
  float* xr = g_x + (size_t)row * Hdim;
  for (int h = threadIdx.x; h < Hdim; h += blockDim.x)
    xr[h] = er[h] + sr[h];
}

// ---------------- Gx = x @ W_ih + b ; M=16384 N=2048 K=512 ------------------
// 128x64 tile, 256 threads, 8 rows x 4 cols per thread via f32x2.
#define GX_PAD 130
__global__ void __launch_bounds__(256) k_gx_gemm(const float* __restrict__ Wih,
                                                 const float* __restrict__ bias){
  __shared__ float As[2][16][GX_PAD];
  __shared__ float Bs[2][16][64];
  int tid = threadIdx.x;
  int m0 = blockIdx.y*128, n0 = blockIdx.x*64;
  int tr = tid>>4, tc = tid&15;
  int s_arow = tid>>2, s_ak = (tid&3)<<2;
  int s_bk = tid>>4, s_bn = (tid&15)<<2;

  const float* Ap = g_x + (size_t)(m0 + s_arow)*Hdim + s_ak;
  const float* Bp = Wih + (size_t)s_bk*G4 + n0 + s_bn;

  float4 ra0 = *(const float4*)Ap;
  float4 ra1 = *(const float4*)(Ap + (size_t)64*Hdim);
  float4 rb  = *(const float4*)Bp;

  u64 acc[4][4];
  #pragma unroll
  for (int r=0;r<4;r++){ acc[r][0]=0; acc[r][1]=0; acc[r][2]=0; acc[r][3]=0; }

  int buf = 0;
  for (int k0 = 0; k0 < Hdim; k0 += 16){
    As[buf][s_ak+0][s_arow]    = ra0.x; As[buf][s_ak+1][s_arow]    = ra0.y;
    As[buf][s_ak+2][s_arow]    = ra0.z; As[buf][s_ak+3][s_arow]    = ra0.w;
    As[buf][s_ak+0][s_arow+64] = ra1.x; As[buf][s_ak+1][s_arow+64] = ra1.y;
    As[buf][s_ak+2][s_arow+64] = ra1.z; As[buf][s_ak+3][s_arow+64] = ra1.w;
    *(float4*)&Bs[buf][s_bk][s_bn] = rb;
    __syncthreads();
    if (k0 + 16 < Hdim){
      Ap += 16; Bp += (size_t)16*G4;
      ra0 = *(const float4*)Ap;
      ra1 = *(const float4*)(Ap + (size_t)64*Hdim);
      rb  = *(const float4*)Bp;
    }
    #pragma unroll
    for (int kk = 0; kk < 16; kk++){
      const float* Ak = &As[buf][kk][tr<<3];
      u64 a0 = *(const u64*)(Ak);
      u64 a1 = *(const u64*)(Ak+2);
      u64 a2 = *(const u64*)(Ak+4);
      u64 a3 = *(const u64*)(Ak+6);
      float4 b = *(const float4*)&Bs[buf][kk][tc<<2];
      u64 b0 = pk2(b.x,b.x), b1 = pk2(b.y,b.y), b2 = pk2(b.z,b.z), b3 = pk2(b.w,b.w);
      acc[0][0]=fma2(a0,b0,acc[0][0]); acc[0][1]=fma2(a0,b1,acc[0][1]);
      acc[0][2]=fma2(a0,b2,acc[0][2]); acc[0][3]=fma2(a0,b3,acc[0][3]);
      acc[1][0]=fma2(a1,b0,acc[1][0]); acc[1][1]=fma2(a1,b1,acc[1][1]);
      acc[1][2]=fma2(a1,b2,acc[1][2]); acc[1][3]=fma2(a1,b3,acc[1][3]);
      acc[2][0]=fma2(a2,b0,acc[2][0]); acc[2][1]=fma2(a2,b1,acc[2][1]);
      acc[2][2]=fma2(a2,b2,acc[2][2]); acc[2][3]=fma2(a2,b3,acc[2][3]);
      acc[3][0]=fma2(a3,b0,acc[3][0]); acc[3][1]=fma2(a3,b1,acc[3][1]);
      acc[3][2]=fma2(a3,b2,acc[3][2]); acc[3][3]=fma2(a3,b3,acc[3][3]);
    }
    buf ^= 1;
  }
  int mrow = m0 + (tr<<3);
  int ncol = n0 + (tc<<2);
  float b0 = bias[ncol], b1 = bias[ncol+1], b2 = bias[ncol+2], b3 = bias[ncol+3];
  #pragma unroll
  for (int rp = 0; rp < 4; rp++){
    float r0c0,r1c0,r0c1,r1c1,r0c2,r1c2,r0c3,r1c3;
    upk2(acc[rp][0], r0c0, r1c0);
    upk2(acc[rp][1], r0c1, r1c1);
    upk2(acc[rp][2], r0c2, r1c2);
    upk2(acc[rp][3], r0c3, r1c3);
    *(float4*)&g_gx[(size_t)(mrow + rp*2    )*G4 + ncol] = make_float4(r0c0+b0, r0c1+b1, r0c2+b2, r0c3+b3);
    *(float4*)&g_gx[(size_t)(mrow + rp*2 + 1)*G4 + ncol] = make_float4(r1c0+b0, r1c1+b1, r1c2+b2, r1c3+b3);
  }
}

// ---------------- persistent LSTM: all 64 steps, split-K, 512 threads -------
// grid = 128 CTAs = 4 row-tiles(64 rows) x 32 hidden-slices(16 units).
// threads: kh = tid>>8 (k-half), th = tid&255 : rg (16 x 4rows) x jh (16 units)
#define AS_PAD 66
#define WS_FLOATS (512*64)
#define SMEM_LSTM ((WS_FLOATS + 2*2*32*AS_PAD) * 4)

extern __shared__ float smem_dyn[];

__global__ void __launch_bounds__(512, 1) k_lstm_persist(const float* __restrict__ Whh){
  float* Ws = smem_dyn;                 // [k][jh*4+g]
  float* As = smem_dyn + WS_FLOATS;     // [buf2][kh2][32][AS_PAD]
  int tid = threadIdx.x;
  int hs = blockIdx.x & 31;
  int mt = blockIdx.x >> 5;
  int m0 = mt << 6;

  // load Whh slice into SMEM once
  {
    int jh = tid & 15, g = (tid>>4)&3, kq = tid>>6;   // kq 0..7
    for (int k = kq; k < 512; k += 8)
      Ws[k*64 + jh*4 + g] = Whh[(size_t)k*G4 + g*512 + hs*16 + jh];
  }
  __syncthreads();

  int kh = tid >> 8;            // k-half 0/1
  int th = tid & 255;
  int rg = th >> 4;             // 0..15 rowgroups of 4
  int jh = th & 15;
  int jglob = hs*16 + jh;
  int r0 = m0 + (rg<<2);
  int khbase = kh << 8;         // 0 / 256

  // A staging map (per half: 256 threads stage 64 rows x 32 k)
  int srow  = th >> 2;          // 0..63
  int skoff = (th & 3) << 3;    // 0,8,16,24

  float cc[4] = {0.f,0.f,0.f,0.f};

  // gx prefetch for step 0 (half-0)
  float pi[4], pf[4], pg[4], po[4];
  if (kh == 0){
    #pragma unroll
    for (int rr = 0; rr < 4; rr++){
      const float* gb = g_gx + (size_t)(r0+rr)*G4 + jglob;
      pi[rr] = __ldcg(gb);
      pf[rr] = __ldcg(gb + 512);
      pg[rr] = __ldcg(gb + 1024);
      po[rr] = __ldcg(gb + 1536);
    }
  }

  for (int t = 0; t < LT; t++){
    const float* hprev = g_h[t & 1];
    float*       hnext = g_h[(t+1) & 1];

    u64 acc[8];
    #pragma unroll
    for (int i=0;i<8;i++) acc[i] = 0ull;

    const float* hrow = hprev + (size_t)(m0+srow)*Hdim + khbase + skoff;
    float4 p0 = __ldcg((const float4*)hrow);
    float4 p1 = __ldcg((const float4*)(hrow + 4));
    int buf = 0;
    for (int c = 0; c < 8; c++){
      float* A = As + (size_t)((buf<<1) + kh)*32*AS_PAD;
      A[(skoff+0)*AS_PAD + srow] = p0.x;
      A[(skoff+1)*AS_PAD + srow] = p0.y;
      A[(skoff+2)*AS_PAD + srow] = p0.z;
      A[(skoff+3)*AS_PAD + srow] = p0.w;
      A[(skoff+4)*AS_PAD + srow] = p1.x;
      A[(skoff+5)*AS_PAD + srow] = p1.y;
      A[(skoff+6)*AS_PAD + srow] = p1.z;
      A[(skoff+7)*AS_PAD + srow] = p1.w;
      __syncthreads();
      if (c < 7){
        p0 = __ldcg((const float4*)(hrow + (c+1)*32));
        p1 = __ldcg((const float4*)(hrow + (c+1)*32 + 4));
      }
      const float* Wk = Ws + (size_t)(khbase + c*32)*64 + (jh<<2);
      #pragma unroll
      for (int kk = 0; kk < 32; kk++){
        const float* Ak = A + kk*AS_PAD + (rg<<2);
        u64 a01 = *(const u64*)(Ak);
        u64 a23 = *(const u64*)(Ak + 2);
        float4 b = *(const float4*)(Wk + kk*64);
        u64 b0 = pk2(b.x,b.x), b1 = pk2(b.y,b.y);
        u64 b2 = pk2(b.z,b.z), b3 = pk2(b.w,b.w);
        acc[0] = fma2(a01,b0,acc[0]); acc[1] = fma2(a23,b0,acc[1]);
        acc[2] = fma2(a01,b1,acc[2]); acc[3] = fma2(a23,b1,acc[3]);
        acc[4] = fma2(a01,b2,acc[4]); acc[5] = fma2(a23,b2,acc[5]);
        acc[6] = fma2(a01,b3,acc[6]); acc[7] = fma2(a23,b3,acc[7]);
      }
      buf ^= 1;
    }

    // cross-half reduction through SMEM (exact fp32 adds)
    __syncthreads();
    u64* red = (u64*)As;
    if (kh == 1){
      #pragma unroll
      for (int i=0;i<8;i++) red[th*8 + i] = acc[i];
    }
    __syncthreads();
    if (kh == 0){
      #pragma unroll
      for (int i=0;i<8;i++) acc[i] = add2(acc[i], red[th*8 + i]);

      float iv[4], fv[4], gv[4], ov[4];
      upk2(acc[0], iv[0], iv[1]); upk2(acc[1], iv[2], iv[3]);
      upk2(acc[2], fv[0], fv[1]); upk2(acc[3], fv[2], fv[3]);
      upk2(acc[4], gv[0], gv[1]); upk2(acc[5], gv[2], gv[3]);
      upk2(acc[6], ov[0], ov[1]); upk2(acc[7], ov[2], ov[3]);
      float* ys = g_ys + (size_t)t*NB*Hdim;
      #pragma unroll
      for (int rr = 0; rr < 4; rr++){
        int n = r0 + rr;
        float i_ = iv[rr] + pi[rr];
        float f_ = fv[rr] + pf[rr];
        float g_ = gv[rr] + pg[rr];
        float o_ = ov[rr] + po[rr];
        float c_ = sigmf_fast(f_)*cc[rr] + sigmf_fast(i_)*tanh_fast(g_);
        float h_ = sigmf_fast(o_)*tanh_fast(c_);
        cc[rr] = c_;
        hnext[(size_t)n*Hdim + jglob] = h_;
        ys   [(size_t)n*Hdim + jglob] = h_;
      }
      // gx prefetch for NEXT step — hides under the barrier wait below
      if (t < LT-1){
        const float* gx = g_gx + (size_t)(t+1)*NB*G4;
        #pragma unroll
        for (int rr = 0; rr < 4; rr++){
          const float* gb = gx + (size_t)(r0+rr)*G4 + jglob;
          pi[rr] = __ldcg(gb);
          pf[rr] = __ldcg(gb + 512);
          pg[rr] = __ldcg(gb + 1024);
          po[rr] = __ldcg(gb + 1536);
        }
      }
    }

    // group barrier over the 32 CTAs sharing this row-tile
    if (t < LT-1){
      __threadfence();
      __syncthreads();
      if (tid == 0){
        atomicAdd(&g_bar4[mt], 1u);
        unsigned target = (unsigned)(t+1) * 32u;
        volatile unsigned* vb = &g_bar4[mt];
        while (*vb < target) { }
      }
      __syncthreads();
    }
  }
}

// ---------------- GNN: build nodes ------------------------------------------
__global__ void k_nodes(){
  int b = blockIdx.x, h = threadIdx.x;
  const float* last = g_ys + (size_t)(LT-1)*NB*Hdim;
  float s = 0.0f;
  for (int u = 0; u < UU; u++){
    float v = last[(size_t)(b*UU + u)*Hdim + h];
    g_nodes[(size_t)(b*NNODE + u)*Hdim + h] = v;
    s += v;
  }
  g_nodes[(size_t)(b*NNODE + UU)*Hdim + h] = s * (1.0f/UU);
}

// ---------------- per-edge message ------------------------------------------
__global__ void __launch_bounds__(256) k_msg(const int* __restrict__ edge_src,
                                             const int* __restrict__ rels,
                                             const float* __restrict__ Wrel){
  int be = blockIdx.x;
  int b = be >> 7;
  int rel = rels[be];
  int es  = edge_src[be];
  __shared__ float xs[Hdim];
  int tid = threadIdx.x;
  xs[tid]     = g_nodes[(size_t)(b*NNODE + es)*Hdim + tid];
  xs[tid+256] = g_nodes[(size_t)(b*NNODE + es)*Hdim + tid + 256];
  __syncthreads();
  const float* W = Wrel + (size_t)rel*Hdim*Hdim;
  float a0 = 0.0f, a1 = 0.0f;
  for (int k = 0; k < Hdim; k++){
    float xv = xs[k];
    a0 += xv * W[(size_t)k*Hdim + tid];
    a1 += xv * W[(size_t)k*Hdim + tid + 256];
  }
  g_msg[(size_t)be*Hdim + tid]       = a0;
  g_msg[(size_t)be*Hdim + tid + 256] = a1;
}

// ---------------- deterministic segment-sum ---------------------------------
__global__ void k_agg(const int* __restrict__ edge_dst){
  int bd = blockIdx.x;
  int b = bd / NNODE, d = bd % NNODE;
  int h = threadIdx.x;
  float a = 0.0f;
  for (int e = 0; e < EE; e++){
    if (edge_dst[b*EE + e] == d)
      a += g_msg[(size_t)(b*EE + e)*Hdim + h];
  }
  g_agg[(size_t)bd*Hdim + h] = a;
}

// ---------------- GNN output/gate fusion ------------------------------------
__global__ void __launch_bounds__(256) k_gnn(const float* __restrict__ Wself,
                                             const float* __restrict__ bg,
                                             const float* __restrict__ Wg1,
                                             const float* __restrict__ Wg2){
  int bd = blockIdx.x;
  __shared__ float nd[Hdim], ag[Hdim];
  int tid = threadIdx.x;
  nd[tid]     = g_nodes[(size_t)bd*Hdim + tid];
  nd[tid+256] = g_nodes[(size_t)bd*Hdim + tid + 256];
  ag[tid]     = g_agg[(size_t)bd*Hdim + tid];
  ag[tid+256] = g_agg[(size_t)bd*Hdim + tid + 256];
  __syncthreads();
  for (int jo = 0; jo < 2; jo++){
    int j = tid + jo*256;
    float s1 = 0.0f, s2 = 0.0f, s3 = 0.0f;
    for (int k = 0; k < Hdim; k++){
      float nv = nd[k], av = ag[k];
      s1 += nv * Wself[(size_t)k*Hdim + j];
      s2 += nv * Wg1  [(size_t)k*Hdim + j];
      s3 += av * Wg2  [(size_t)k*Hdim + j];
    }
    float outv = s1 + ag[j] + bg[j];
    outv = outv > 0.0f ? outv : 0.0f;
    float gate = sigmf(s2 + s3);
    g_new[(size_t)bd*Hdim + j] = gate*outv + (1.0f - gate)*nd[j];
  }
}

// ---------------- output writers --------------------------------------------
__global__ void k_out_small(float* __restrict__ dout, const int* __restrict__ lengths){
  int i = blockIdx.x*blockDim.x + threadIdx.x;
  if (i < 4096){
    int b = i >> 9, h = i & 511;
    float v = g_new[(size_t)(b*NNODE + UU)*Hdim + h];
    dout[OFF_ENCH + i] = v;
    dout[OFF_ENCC + i] = v;
  }
  if (i < 8){
    float lv = (float)lengths[i];
    dout[OFF_LEN1 + i] = lv;
    dout[OFF_LEN2 + i] = lv;
  }
  dout[OFF_HIER + i] = (float)LT;
}

__global__ void k_big_out(float* __restrict__ dout){
  size_t i = (size_t)blockIdx.x*blockDim.x + threadIdx.x;
  if (i >= (size_t)SS*BB*Hdim) return;
  int h = (int)(i & 511);
  int b = (int)((i >> 9) & 7);
  int s = (int)(i >> 12);
  int t = s & 63, u = s >> 6;
  dout[OFF_MB  + i] = g_ys[((size_t)t*NB + b*UU + u)*Hdim + h];
  dout[OFF_MBU + i] = g_new[(size_t)(b*NNODE + u)*Hdim + h];
}

// ---------------- driver -----------------------------------------------------
extern "C" void kernel_launch(void* const* d_in, const int* in_sizes, int n_in,
                              void* d_out, int out_size){
  const int*   src      = (const int*)  d_in[0];
  const int*   speaker  = (const int*)  d_in[2];
  const int*   lengths  = (const int*)  d_in[3];
  const int*   edge_src = (const int*)  d_in[4];
  const int*   edge_dst = (const int*)  d_in[5];
  const int*   rels     = (const int*)  d_in[6];
  const float* emb      = (const float*)d_in[7];
  const float* spkt     = (const float*)d_in[8];
  const float* Wih      = (const float*)d_in[9];
  const float* Whh      = (const float*)d_in[10];
  const float* bl       = (const float*)d_in[11];
  const float* Wrel     = (const float*)d_in[12];
  const float* Wself    = (const float*)d_in[13];
  const float* bg       = (const float*)d_in[14];
  const float* Wg1      = (const float*)d_in[15];
  const float* Wg2      = (const float*)d_in[16];
  float* dout = (float*)d_out;

  cudaFuncSetAttribute(k_lstm_persist, cudaFuncAttributeMaxDynamicSharedMemorySize, SMEM_LSTM);

  k_zero<<<512, 256>>>();
  k_embed<<<LT*NB, 256>>>(src, speaker, emb, spkt);
  k_gx_gemm<<<dim3(G4/64, (LT*NB)/128), 256>>>(Wih, bl);
  k_lstm_persist<<<LSTM_GRID, 512, SMEM_LSTM>>>(Whh);
  k_nodes<<<BB, 512>>>();
  k_msg<<<BB*EE, 256>>>(edge_src, rels, Wrel);
  k_agg<<<BB*NNODE, 512>>>(edge_dst);
  k_gnn<<<BB*NNODE, 256>>>(Wself, bg, Wg1, Wg2);
  k_out_small<<<64, 256>>>(dout, lengths);
  k_big_out<<<32768, 256>>>(dout);
}